// round 1
// baseline (speedup 1.0000x reference)
#include <cuda_runtime.h>
#include <math.h>

#define BATCH 2
#define SEQ   2048
#define DMODEL 1024
#define NHEAD 16
#define HDIM  64
#define D3    3072   // 3 * DMODEL

// Scratch buffers (allocation-free rule: __device__ globals)
__device__ float g_qkv[(size_t)BATCH * SEQ * D3];     // [B,S,3D], e = h*192 + {q:0..63, k:64..127, v:128..191}
__device__ float g_vals[(size_t)BATCH * SEQ * DMODEL]; // [B,S,D], d = h*64 + hd

// ---------------------------------------------------------------------------
// SGEMM: C[M,N] = A[M,K] @ B[N,K]^T + bias[N]
// A row-major [M,K], Bm row-major [N,K] (reduction along K for both).
// 128x128 tile, BK=8, 256 threads, 8x8 per-thread micro-tile.
// ---------------------------------------------------------------------------
#define GBM 128
#define GBN 128
#define GBK 8
#define GPAD 4   // smem row pad: (128+4)=132 words; 4*132 = 528 = 16 mod 32 -> conflict-free stores

__global__ __launch_bounds__(256) void sgemm_nt(const float* __restrict__ A,
                                                const float* __restrict__ Bm,
                                                const float* __restrict__ bias,
                                                float* __restrict__ C,
                                                int M, int N, int K) {
    __shared__ float As[GBK][GBM + GPAD];
    __shared__ float Bs[GBK][GBN + GPAD];

    const int tid = threadIdx.x;
    const int tx = tid & 15;       // 0..15 -> N micro
    const int ty = tid >> 4;       // 0..15 -> M micro
    const int row0 = blockIdx.y * GBM;
    const int col0 = blockIdx.x * GBN;

    // global-load mapping: 256 threads, each loads one float4 of A and of B per k-step
    const int lrow = tid >> 1;          // 0..127
    const int lk   = (tid & 1) << 2;    // 0 or 4

    const float* Ap = A + (size_t)(row0 + lrow) * K + lk;
    const float* Bp = Bm + (size_t)(col0 + lrow) * K + lk;

    float acc[8][8];
#pragma unroll
    for (int i = 0; i < 8; ++i)
#pragma unroll
        for (int j = 0; j < 8; ++j) acc[i][j] = 0.0f;

    for (int k0 = 0; k0 < K; k0 += GBK) {
        float4 av = *(const float4*)(Ap + k0);
        float4 bv = *(const float4*)(Bp + k0);
        As[lk + 0][lrow] = av.x; As[lk + 1][lrow] = av.y;
        As[lk + 2][lrow] = av.z; As[lk + 3][lrow] = av.w;
        Bs[lk + 0][lrow] = bv.x; Bs[lk + 1][lrow] = bv.y;
        Bs[lk + 2][lrow] = bv.z; Bs[lk + 3][lrow] = bv.w;
        __syncthreads();

#pragma unroll
        for (int kk = 0; kk < GBK; ++kk) {
            float4 a0 = *(const float4*)&As[kk][ty * 8];
            float4 a1 = *(const float4*)&As[kk][ty * 8 + 4];
            float4 b0 = *(const float4*)&Bs[kk][tx * 8];
            float4 b1 = *(const float4*)&Bs[kk][tx * 8 + 4];
            float a[8] = {a0.x, a0.y, a0.z, a0.w, a1.x, a1.y, a1.z, a1.w};
            float b[8] = {b0.x, b0.y, b0.z, b0.w, b1.x, b1.y, b1.z, b1.w};
#pragma unroll
            for (int i = 0; i < 8; ++i)
#pragma unroll
                for (int j = 0; j < 8; ++j)
                    acc[i][j] += a[i] * b[j];
        }
        __syncthreads();
    }

    // epilogue with bias
    float4 bb0 = *(const float4*)(bias + col0 + tx * 8);
    float4 bb1 = *(const float4*)(bias + col0 + tx * 8 + 4);
    const float bvals[8] = {bb0.x, bb0.y, bb0.z, bb0.w, bb1.x, bb1.y, bb1.z, bb1.w};
#pragma unroll
    for (int i = 0; i < 8; ++i) {
        float* cp = C + (size_t)(row0 + ty * 8 + i) * N + col0 + tx * 8;
        float4 o0 = make_float4(acc[i][0] + bvals[0], acc[i][1] + bvals[1],
                                acc[i][2] + bvals[2], acc[i][3] + bvals[3]);
        float4 o1 = make_float4(acc[i][4] + bvals[4], acc[i][5] + bvals[5],
                                acc[i][6] + bvals[6], acc[i][7] + bvals[7]);
        *(float4*)(cp) = o0;
        *(float4*)(cp + 4) = o1;
    }
}

// ---------------------------------------------------------------------------
// Flash attention, fp32. One CTA = 64 q-rows of one (b,h); loop over 64-wide
// K/V tiles with online softmax. 256 threads, 4x4 micro-tiles.
// Smem (dynamic): Qt[d][r], Kt[d][j] (transposed for float4 a/b frags),
// Vs[j][d], Pt[j][r]. Row stride 68 floats (272B: 16B-aligned rows).
// ---------------------------------------------------------------------------
#define APAD 68
#define ATTN_SMEM (4 * 64 * APAD * (int)sizeof(float))   // 69632 B

__global__ __launch_bounds__(256) void attn_kernel() {
    extern __shared__ float smem[];
    float* Qt = smem;                 // [64][68] : Qt[d][r]  (q pre-scaled by 1/8)
    float* Kt = Qt + 64 * APAD;       // [64][68] : Kt[d][j]
    float* Vs = Kt + 64 * APAD;       // [64][68] : Vs[j][d]
    float* Pt = Vs + 64 * APAD;       // [64][68] : Pt[j][r]

    const int tid = threadIdx.x;
    const int tx = tid & 15;          // k-col / out-dim micro
    const int ty = tid >> 4;          // q-row micro
    const int bh = blockIdx.y;
    const int b = bh >> 4;
    const int h = bh & 15;
    const int q0 = blockIdx.x * 64;

    const size_t base = (size_t)b * SEQ * D3 + (size_t)h * (3 * HDIM);

    // load Q tile transposed, pre-scaled by 1/sqrt(64)=0.125
    {
        const int r = tid >> 2;
        const int d0 = (tid & 3) << 4;
        const float* p = g_qkv + base + (size_t)(q0 + r) * D3 + d0;
#pragma unroll
        for (int c = 0; c < 16; c += 4) {
            float4 v = *(const float4*)(p + c);
            Qt[(d0 + c + 0) * APAD + r] = v.x * 0.125f;
            Qt[(d0 + c + 1) * APAD + r] = v.y * 0.125f;
            Qt[(d0 + c + 2) * APAD + r] = v.z * 0.125f;
            Qt[(d0 + c + 3) * APAD + r] = v.w * 0.125f;
        }
    }

    float acc[4][4];
#pragma unroll
    for (int i = 0; i < 4; ++i)
#pragma unroll
        for (int j = 0; j < 4; ++j) acc[i][j] = 0.0f;
    float m_i[4], l_i[4];
#pragma unroll
    for (int i = 0; i < 4; ++i) { m_i[i] = -1e30f; l_i[i] = 0.0f; }

    const int r = tid >> 2;
    const int d0 = (tid & 3) << 4;

    for (int k0 = 0; k0 < SEQ; k0 += 64) {
        // prefetch K/V tile rows to registers (before sync: no smem deps)
        const float* kp = g_qkv + base + 64 + (size_t)(k0 + r) * D3 + d0;
        const float* vp = kp + 64;
        float4 kv[4], vv[4];
#pragma unroll
        for (int c = 0; c < 4; ++c) {
            kv[c] = *(const float4*)(kp + 4 * c);
            vv[c] = *(const float4*)(vp + 4 * c);
        }

        __syncthreads();   // previous iteration's PV (Pt,Vs readers) done
#pragma unroll
        for (int c = 0; c < 4; ++c) {
            Kt[(d0 + 4 * c + 0) * APAD + r] = kv[c].x;
            Kt[(d0 + 4 * c + 1) * APAD + r] = kv[c].y;
            Kt[(d0 + 4 * c + 2) * APAD + r] = kv[c].z;
            Kt[(d0 + 4 * c + 3) * APAD + r] = kv[c].w;
            *(float4*)&Vs[r * APAD + d0 + 4 * c] = vv[c];
        }
        __syncthreads();

        // S = (Q*scale) @ K^T  -> 4x4 per thread
        float s[4][4];
#pragma unroll
        for (int i = 0; i < 4; ++i)
#pragma unroll
            for (int j = 0; j < 4; ++j) s[i][j] = 0.0f;
#pragma unroll 16
        for (int d = 0; d < 64; ++d) {
            float4 aq = *(const float4*)&Qt[d * APAD + ty * 4];
            float4 bk = *(const float4*)&Kt[d * APAD + tx * 4];
            float a[4] = {aq.x, aq.y, aq.z, aq.w};
            float kb[4] = {bk.x, bk.y, bk.z, bk.w};
#pragma unroll
            for (int i = 0; i < 4; ++i)
#pragma unroll
                for (int j = 0; j < 4; ++j)
                    s[i][j] += a[i] * kb[j];
        }

        // online softmax update (row stats across the 16 tx lanes of each row)
#pragma unroll
        for (int i = 0; i < 4; ++i) {
            float rm = fmaxf(fmaxf(s[i][0], s[i][1]), fmaxf(s[i][2], s[i][3]));
            rm = fmaxf(rm, __shfl_xor_sync(0xffffffffu, rm, 1));
            rm = fmaxf(rm, __shfl_xor_sync(0xffffffffu, rm, 2));
            rm = fmaxf(rm, __shfl_xor_sync(0xffffffffu, rm, 4));
            rm = fmaxf(rm, __shfl_xor_sync(0xffffffffu, rm, 8));
            float mnew = fmaxf(m_i[i], rm);
            float alpha = __expf(m_i[i] - mnew);
            float p0 = __expf(s[i][0] - mnew);
            float p1 = __expf(s[i][1] - mnew);
            float p2 = __expf(s[i][2] - mnew);
            float p3 = __expf(s[i][3] - mnew);
            s[i][0] = p0; s[i][1] = p1; s[i][2] = p2; s[i][3] = p3;
            float sum = p0 + p1 + p2 + p3;
            sum += __shfl_xor_sync(0xffffffffu, sum, 1);
            sum += __shfl_xor_sync(0xffffffffu, sum, 2);
            sum += __shfl_xor_sync(0xffffffffu, sum, 4);
            sum += __shfl_xor_sync(0xffffffffu, sum, 8);
            l_i[i] = l_i[i] * alpha + sum;
            m_i[i] = mnew;
            acc[i][0] *= alpha; acc[i][1] *= alpha;
            acc[i][2] *= alpha; acc[i][3] *= alpha;
        }

        // write P transposed: Pt[j][r]
#pragma unroll
        for (int j = 0; j < 4; ++j)
#pragma unroll
            for (int i = 0; i < 4; ++i)
                Pt[(tx * 4 + j) * APAD + ty * 4 + i] = s[i][j];
        __syncthreads();

        // O += P @ V
#pragma unroll 16
        for (int j = 0; j < 64; ++j) {
            float4 ap = *(const float4*)&Pt[j * APAD + ty * 4];
            float4 bv = *(const float4*)&Vs[j * APAD + tx * 4];
            float a[4] = {ap.x, ap.y, ap.z, ap.w};
            float vb[4] = {bv.x, bv.y, bv.z, bv.w};
#pragma unroll
            for (int i = 0; i < 4; ++i)
#pragma unroll
                for (int jj = 0; jj < 4; ++jj)
                    acc[i][jj] += a[i] * vb[jj];
        }
    }

    // epilogue: normalize and store to g_vals[b, s, h*64 + od]
#pragma unroll
    for (int i = 0; i < 4; ++i) {
        float inv = 1.0f / l_i[i];
        size_t row = (size_t)b * SEQ + q0 + ty * 4 + i;
        float4 o = make_float4(acc[i][0] * inv, acc[i][1] * inv,
                               acc[i][2] * inv, acc[i][3] * inv);
        *(float4*)(g_vals + row * DMODEL + h * HDIM + tx * 4) = o;
    }
}

// ---------------------------------------------------------------------------
// launch
// ---------------------------------------------------------------------------
extern "C" void kernel_launch(void* const* d_in, const int* in_sizes, int n_in,
                              void* d_out, int out_size) {
    const float* x     = (const float*)d_in[0];  // [B,S,D]
    const float* qkv_w = (const float*)d_in[1];  // [3D,D]
    const float* qkv_b = (const float*)d_in[2];  // [3D]
    const float* o_w   = (const float*)d_in[3];  // [D,D]
    const float* o_b   = (const float*)d_in[4];  // [D]
    float* out = (float*)d_out;                  // [B,S,D]

    float* qkvbuf = nullptr;
    float* valsbuf = nullptr;
    cudaGetSymbolAddress((void**)&qkvbuf, g_qkv);
    cudaGetSymbolAddress((void**)&valsbuf, g_vals);

    cudaFuncSetAttribute(attn_kernel, cudaFuncAttributeMaxDynamicSharedMemorySize,
                         ATTN_SMEM);

    const int M = BATCH * SEQ;  // 4096

    // 1) QKV projection: [4096,3072] = x[4096,1024] @ qkv_w[3072,1024]^T
    {
        dim3 grid(D3 / GBN, M / GBM);   // (24, 32)
        sgemm_nt<<<grid, 256>>>(x, qkv_w, qkv_b, qkvbuf, M, D3, DMODEL);
    }

    // 2) attention
    {
        dim3 grid(SEQ / 64, BATCH * NHEAD);  // (32, 32)
        attn_kernel<<<grid, 256, ATTN_SMEM>>>();
    }

    // 3) output projection: out[4096,1024] = vals[4096,1024] @ o_w[1024,1024]^T
    {
        dim3 grid(DMODEL / GBN, M / GBM);  // (8, 32)
        sgemm_nt<<<grid, 256>>>(valsbuf, o_w, o_b, out, M, DMODEL, DMODEL);
    }
}

// round 10
// speedup vs baseline: 2.0857x; 2.0857x over previous
#include <cuda_runtime.h>
#include <math.h>
#include <stdint.h>

#define BATCH 2
#define SEQ   2048
#define DMODEL 1024
#define NHEAD 16
#define HDIM  64
#define D3    3072   // 3 * DMODEL

// Scratch buffers (allocation-free rule: __device__ globals)
__device__ float g_qkv[(size_t)BATCH * SEQ * D3];      // [B,S,3D]
__device__ float g_vals[(size_t)BATCH * SEQ * DMODEL]; // [B,S,D]

__device__ __forceinline__ uint32_t f2tf32(float x) {
    uint32_t y;
    asm("cvt.rna.tf32.f32 %0, %1;" : "=r"(y) : "f"(x));
    return y;
}

__device__ __forceinline__ void mma_tf32(float c[4],
                                         uint32_t a0, uint32_t a1, uint32_t a2, uint32_t a3,
                                         uint32_t b0, uint32_t b1) {
    asm volatile(
        "mma.sync.aligned.m16n8k8.row.col.f32.tf32.tf32.f32 "
        "{%0,%1,%2,%3}, {%4,%5,%6,%7}, {%8,%9}, {%0,%1,%2,%3};\n"
        : "+f"(c[0]), "+f"(c[1]), "+f"(c[2]), "+f"(c[3])
        : "r"(a0), "r"(a1), "r"(a2), "r"(a3), "r"(b0), "r"(b1));
}

// ---------------------------------------------------------------------------
// TF32 tensor-core GEMM: C[M,N] = A[M,K] @ Bm[N,K]^T + bias[N]
// CTA tile 128x128, BK=32, 256 threads = 8 warps (2x4), warp tile 64x32.
// ---------------------------------------------------------------------------
#define TBM 128
#define TBN 128
#define TBK 32
#define TPAD 8     // stride 136: 136%32=8 -> frag-load banks = 8*tg+g, conflict-free

__global__ __launch_bounds__(256) void sgemm_tf32(const float* __restrict__ A,
                                                  const float* __restrict__ Bm,
                                                  const float* __restrict__ bias,
                                                  float* __restrict__ C,
                                                  int M, int N, int K) {
    __shared__ uint32_t As[TBK][TBM + TPAD];   // As[k][m]
    __shared__ uint32_t Bs[TBK][TBN + TPAD];   // Bs[k][n]

    const int tid  = threadIdx.x;
    const int lane = tid & 31;
    const int g    = lane >> 2;   // groupID 0..7
    const int tg   = lane & 3;    // thread-in-group 0..3
    const int warp = tid >> 5;
    const int wm   = (warp >> 2) * 64;  // 0 or 64
    const int wn   = (warp & 3) * 32;   // 0,32,64,96

    const int row0 = blockIdx.y * TBM;
    const int col0 = blockIdx.x * TBN;

    const int r  = tid & 127;
    const int kq = (tid >> 7) << 2;   // 0 or 4

    const float* Ap = A + (size_t)(row0 + r) * K + kq;
    const float* Bp = Bm + (size_t)(col0 + r) * K + kq;

    float c[4][4][4];
#pragma unroll
    for (int mt = 0; mt < 4; ++mt)
#pragma unroll
        for (int nt = 0; nt < 4; ++nt)
#pragma unroll
            for (int i = 0; i < 4; ++i) c[mt][nt][i] = 0.0f;

    for (int k0 = 0; k0 < K; k0 += TBK) {
        float4 av[4], bv[4];
#pragma unroll
        for (int j = 0; j < 4; ++j) {
            av[j] = *(const float4*)(Ap + k0 + j * 8);
            bv[j] = *(const float4*)(Bp + k0 + j * 8);
        }
        __syncthreads();
#pragma unroll
        for (int j = 0; j < 4; ++j) {
            const int kb = kq + j * 8;
            As[kb + 0][r] = f2tf32(av[j].x);
            As[kb + 1][r] = f2tf32(av[j].y);
            As[kb + 2][r] = f2tf32(av[j].z);
            As[kb + 3][r] = f2tf32(av[j].w);
            Bs[kb + 0][r] = f2tf32(bv[j].x);
            Bs[kb + 1][r] = f2tf32(bv[j].y);
            Bs[kb + 2][r] = f2tf32(bv[j].z);
            Bs[kb + 3][r] = f2tf32(bv[j].w);
        }
        __syncthreads();

#pragma unroll
        for (int ks = 0; ks < TBK / 8; ++ks) {
            const int kb = ks * 8;
            uint32_t af[4][4], bf[4][2];
#pragma unroll
            for (int mt = 0; mt < 4; ++mt) {
                const int m = wm + mt * 16 + g;
                af[mt][0] = As[kb + tg][m];
                af[mt][1] = As[kb + tg][m + 8];
                af[mt][2] = As[kb + tg + 4][m];
                af[mt][3] = As[kb + tg + 4][m + 8];
            }
#pragma unroll
            for (int nt = 0; nt < 4; ++nt) {
                const int n = wn + nt * 8 + g;
                bf[nt][0] = Bs[kb + tg][n];
                bf[nt][1] = Bs[kb + tg + 4][n];
            }
#pragma unroll
            for (int mt = 0; mt < 4; ++mt)
#pragma unroll
                for (int nt = 0; nt < 4; ++nt)
                    mma_tf32(c[mt][nt], af[mt][0], af[mt][1], af[mt][2], af[mt][3],
                             bf[nt][0], bf[nt][1]);
        }
    }

#pragma unroll
    for (int mt = 0; mt < 4; ++mt) {
        const int rr = row0 + wm + mt * 16 + g;
#pragma unroll
        for (int nt = 0; nt < 4; ++nt) {
            const int cc = col0 + wn + nt * 8 + tg * 2;
            const float b0v = bias[cc];
            const float b1v = bias[cc + 1];
            float2 v0 = make_float2(c[mt][nt][0] + b0v, c[mt][nt][1] + b1v);
            float2 v1 = make_float2(c[mt][nt][2] + b0v, c[mt][nt][3] + b1v);
            *(float2*)(C + (size_t)rr * N + cc) = v0;
            *(float2*)(C + (size_t)(rr + 8) * N + cc) = v1;
        }
    }
}

// ---------------------------------------------------------------------------
// Flash attention with TF32 mma. CTA = 128 q rows of one (b,h); K-tiles of 64.
// 8 warps; warp w owns q rows [16w,16w+16). Online softmax on C-fragments.
// Smem layouts (uint32 tf32 payloads):
//   Qt[d][q]  stride 136   (A-operand of QK^T, k-major = d)
//   Kt[d][k]  stride 72    (B-operand of QK^T)
//   Vs[j][d]  stride 72    (B-operand of PV, k-major = j)
//   Pt[j][q]  stride 136   (A-operand of PV; rows warp-private)
// strides % 32 == 8 -> fragment LDS banks = 8*tg + g : conflict-free.
// ---------------------------------------------------------------------------
#define ABM 128
#define QSTR (128 + 8)   // 136
#define KSTR (64 + 8)    // 72
#define ATTN_SMEM ((2 * 64 * QSTR + 2 * 64 * KSTR) * (int)sizeof(uint32_t))  // 106496 B

__global__ __launch_bounds__(256) void attn_tc() {
    extern __shared__ uint32_t sm[];
    uint32_t* Qt = sm;                  // [64][136]
    uint32_t* Kt = Qt + 64 * QSTR;      // [64][72]
    uint32_t* Vs = Kt + 64 * KSTR;      // [64][72]
    uint32_t* Pt = Vs + 64 * KSTR;      // [64][136]

    const int tid  = threadIdx.x;
    const int lane = tid & 31;
    const int g    = lane >> 2;
    const int tg   = lane & 3;
    const int w    = tid >> 5;
    const int m    = 16 * w + g;        // this thread's first q-row (second is m+8)

    const int b  = blockIdx.y >> 4;
    const int h  = blockIdx.y & 15;
    const int q0 = blockIdx.x * ABM;

    const size_t base = (size_t)b * SEQ * D3 + (size_t)h * (3 * HDIM);

    // ---- load Q tile (scaled by 1/8, tf32) into Qt[d][q] ----
    {
        const int r  = tid & 127;
        const int dh = (tid >> 7) * 32;
        const float* qp = g_qkv + base + (size_t)(q0 + r) * D3 + dh;
#pragma unroll
        for (int i = 0; i < 32; i += 4) {
            float4 v = *(const float4*)(qp + i);
            Qt[(dh + i + 0) * QSTR + r] = f2tf32(v.x * 0.125f);
            Qt[(dh + i + 1) * QSTR + r] = f2tf32(v.y * 0.125f);
            Qt[(dh + i + 2) * QSTR + r] = f2tf32(v.z * 0.125f);
            Qt[(dh + i + 3) * QSTR + r] = f2tf32(v.w * 0.125f);
        }
    }

    float co[8][4];
#pragma unroll
    for (int nf = 0; nf < 8; ++nf)
#pragma unroll
        for (int i = 0; i < 4; ++i) co[nf][i] = 0.0f;
    float m0 = -1e30f, m1 = -1e30f, l0 = 0.0f, l1 = 0.0f;

    // K/V loader mapping
    const int jj = tid & 63;
    const int dq = (tid >> 6) * 16;
    const float* kbase = g_qkv + base + 64 + (size_t)jj * D3 + dq;

    for (int k0 = 0; k0 < SEQ; k0 += 64) {
        // prefetch K/V tile (no smem dependency yet)
        float4 kv[4], vv[4];
        const float* kp = kbase + (size_t)k0 * D3;
#pragma unroll
        for (int c = 0; c < 4; ++c) {
            kv[c] = *(const float4*)(kp + 4 * c);
            vv[c] = *(const float4*)(kp + 64 + 4 * c);
        }

        __syncthreads();   // all warps done with previous tile's Kt/Vs reads
#pragma unroll
        for (int c = 0; c < 4; ++c) {
            const int d = dq + 4 * c;
            Kt[(d + 0) * KSTR + jj] = f2tf32(kv[c].x);
            Kt[(d + 1) * KSTR + jj] = f2tf32(kv[c].y);
            Kt[(d + 2) * KSTR + jj] = f2tf32(kv[c].z);
            Kt[(d + 3) * KSTR + jj] = f2tf32(kv[c].w);
            uint4 vt;
            vt.x = f2tf32(vv[c].x); vt.y = f2tf32(vv[c].y);
            vt.z = f2tf32(vv[c].z); vt.w = f2tf32(vv[c].w);
            *(uint4*)&Vs[jj * KSTR + d] = vt;
        }
        __syncthreads();

        // ---- S = Q @ K^T  (warp: 16 x 64) ----
        float cs[8][4];
#pragma unroll
        for (int nf = 0; nf < 8; ++nf)
#pragma unroll
            for (int i = 0; i < 4; ++i) cs[nf][i] = 0.0f;

#pragma unroll
        for (int ks = 0; ks < 8; ++ks) {
            const int kb = ks * 8;
            uint32_t a0 = Qt[(kb + tg) * QSTR + m];
            uint32_t a1 = Qt[(kb + tg) * QSTR + m + 8];
            uint32_t a2 = Qt[(kb + tg + 4) * QSTR + m];
            uint32_t a3 = Qt[(kb + tg + 4) * QSTR + m + 8];
#pragma unroll
            for (int nf = 0; nf < 8; ++nf) {
                uint32_t b0 = Kt[(kb + tg) * KSTR + nf * 8 + g];
                uint32_t b1 = Kt[(kb + tg + 4) * KSTR + nf * 8 + g];
                mma_tf32(cs[nf], a0, a1, a2, a3, b0, b1);
            }
        }

        // ---- online softmax on fragment rows (m) and (m+8) ----
        float rmax0 = -1e30f, rmax1 = -1e30f;
#pragma unroll
        for (int nf = 0; nf < 8; ++nf) {
            rmax0 = fmaxf(rmax0, fmaxf(cs[nf][0], cs[nf][1]));
            rmax1 = fmaxf(rmax1, fmaxf(cs[nf][2], cs[nf][3]));
        }
        rmax0 = fmaxf(rmax0, __shfl_xor_sync(0xffffffffu, rmax0, 1));
        rmax0 = fmaxf(rmax0, __shfl_xor_sync(0xffffffffu, rmax0, 2));
        rmax1 = fmaxf(rmax1, __shfl_xor_sync(0xffffffffu, rmax1, 1));
        rmax1 = fmaxf(rmax1, __shfl_xor_sync(0xffffffffu, rmax1, 2));

        const float mn0 = fmaxf(m0, rmax0);
        const float mn1 = fmaxf(m1, rmax1);
        const float a0s = __expf(m0 - mn0);
        const float a1s = __expf(m1 - mn1);
        float sum0 = 0.0f, sum1 = 0.0f;
#pragma unroll
        for (int nf = 0; nf < 8; ++nf) {
            cs[nf][0] = __expf(cs[nf][0] - mn0);
            cs[nf][1] = __expf(cs[nf][1] - mn0);
            cs[nf][2] = __expf(cs[nf][2] - mn1);
            cs[nf][3] = __expf(cs[nf][3] - mn1);
            sum0 += cs[nf][0] + cs[nf][1];
            sum1 += cs[nf][2] + cs[nf][3];
        }
        sum0 += __shfl_xor_sync(0xffffffffu, sum0, 1);
        sum0 += __shfl_xor_sync(0xffffffffu, sum0, 2);
        sum1 += __shfl_xor_sync(0xffffffffu, sum1, 1);
        sum1 += __shfl_xor_sync(0xffffffffu, sum1, 2);
        l0 = l0 * a0s + sum0;
        l1 = l1 * a1s + sum1;
        m0 = mn0;
        m1 = mn1;
#pragma unroll
        for (int nf = 0; nf < 8; ++nf) {
            co[nf][0] *= a0s; co[nf][1] *= a0s;
            co[nf][2] *= a1s; co[nf][3] *= a1s;
        }

        // ---- write P (tf32) to Pt[j][q]; rows are warp-private ----
#pragma unroll
        for (int nf = 0; nf < 8; ++nf) {
            const int jc = nf * 8 + 2 * tg;
            Pt[jc * QSTR + m]           = f2tf32(cs[nf][0]);
            Pt[(jc + 1) * QSTR + m]     = f2tf32(cs[nf][1]);
            Pt[jc * QSTR + m + 8]       = f2tf32(cs[nf][2]);
            Pt[(jc + 1) * QSTR + m + 8] = f2tf32(cs[nf][3]);
        }
        __syncwarp();

        // ---- O += P @ V  (warp: 16 x 64) ----
#pragma unroll
        for (int ks = 0; ks < 8; ++ks) {
            const int kb = ks * 8;
            uint32_t a0 = Pt[(kb + tg) * QSTR + m];
            uint32_t a1 = Pt[(kb + tg) * QSTR + m + 8];
            uint32_t a2 = Pt[(kb + tg + 4) * QSTR + m];
            uint32_t a3 = Pt[(kb + tg + 4) * QSTR + m + 8];
#pragma unroll
            for (int nf = 0; nf < 8; ++nf) {
                uint32_t b0 = Vs[(kb + tg) * KSTR + nf * 8 + g];
                uint32_t b1 = Vs[(kb + tg + 4) * KSTR + nf * 8 + g];
                mma_tf32(co[nf], a0, a1, a2, a3, b0, b1);
            }
        }
    }

    // ---- epilogue: normalize, store to g_vals[b, q, h*64 + d] ----
    const float inv0 = 1.0f / l0;
    const float inv1 = 1.0f / l1;
    const size_t row0 = (size_t)b * SEQ + q0 + m;
#pragma unroll
    for (int nf = 0; nf < 8; ++nf) {
        const int col = h * HDIM + nf * 8 + 2 * tg;
        float2 v0 = make_float2(co[nf][0] * inv0, co[nf][1] * inv0);
        float2 v1 = make_float2(co[nf][2] * inv1, co[nf][3] * inv1);
        *(float2*)(g_vals + row0 * DMODEL + col) = v0;
        *(float2*)(g_vals + (row0 + 8) * DMODEL + col) = v1;
    }
}

// ---------------------------------------------------------------------------
// launch
// ---------------------------------------------------------------------------
extern "C" void kernel_launch(void* const* d_in, const int* in_sizes, int n_in,
                              void* d_out, int out_size) {
    const float* x     = (const float*)d_in[0];  // [B,S,D]
    const float* qkv_w = (const float*)d_in[1];  // [3D,D]
    const float* qkv_b = (const float*)d_in[2];  // [3D]
    const float* o_w   = (const float*)d_in[3];  // [D,D]
    const float* o_b   = (const float*)d_in[4];  // [D]
    float* out = (float*)d_out;                  // [B,S,D]

    float* qkvbuf = nullptr;
    float* valsbuf = nullptr;
    cudaGetSymbolAddress((void**)&qkvbuf, g_qkv);
    cudaGetSymbolAddress((void**)&valsbuf, g_vals);

    cudaFuncSetAttribute(attn_tc, cudaFuncAttributeMaxDynamicSharedMemorySize,
                         ATTN_SMEM);

    const int M = BATCH * SEQ;  // 4096

    // 1) QKV projection: [4096,3072] = x[4096,1024] @ qkv_w[3072,1024]^T
    {
        dim3 grid(D3 / TBN, M / TBM);   // (24, 32)
        sgemm_tf32<<<grid, 256>>>(x, qkv_w, qkv_b, qkvbuf, M, D3, DMODEL);
    }

    // 2) attention
    {
        dim3 grid(SEQ / ABM, BATCH * NHEAD);  // (16, 32)
        attn_tc<<<grid, 256, ATTN_SMEM>>>();
    }

    // 3) output projection: out[4096,1024] = vals[4096,1024] @ o_w[1024,1024]^T
    {
        dim3 grid(DMODEL / TBN, M / TBM);  // (8, 32)
        sgemm_tf32<<<grid, 256>>>(valsbuf, o_w, o_b, out, M, DMODEL, DMODEL);
    }
}